// round 7
// baseline (speedup 1.0000x reference)
#include <cuda_runtime.h>
#include <cfloat>

// ---------------------------------------------------------------------------
// ResidualVQ on GB300 — round 2: fp32 SGEMM pipeline with bit-faithful
// replication of the reference's distance computation.
//
// Key insight: reference dist = (||enc||^2 - 2*enc.cb) + ||cb||^2 in fp32,
// where ||enc||^2 ~ 1e8 quantizes the dist to ulp ~ 8 while best-gap ~ 5e3.
// The argmin is decided by that rounding for ~1e-3 of decisions, and a single
// flipped token costs ~0.4% L2 error. So we must reproduce the exact fp32
// rounding: ascending-k single-accumulator fma GEMMs (matches Eigen/cublas),
// sequential scalar mul+add row sums for ||enc||^2 / ||cb||^2, and the exact
// op sequence fadd(fsub(enc2, fmul(2,dot)), cbn) with contraction disabled.
// ---------------------------------------------------------------------------

#define BM 128
#define BN 128
#define BK 16

#define MTOK 16384
#define TDIM 2048
#define DIN  768
#define RVQn 512
#define NQn  8
#define CSn  1024
#define CDn  256
#define DOUT 768

// scratch (device globals; no allocation allowed)
__device__ float g_x   [MTOK * RVQn];   // input-proj output (kept for emb = x - res)
__device__ float g_res [MTOK * RVQn];   // running residual
__device__ float g_enc [MTOK * CDn];    // per-stage encoding
__device__ float g_enc2[MTOK];          // per-token ||enc||^2
__device__ float g_cbn [CSn];           // per-stage codebook norms
__device__ int   g_idx [MTOK];          // per-stage argmin indices

// ---------------------------------------------------------------------------
// Unified SGEMM: C[m,n] = sum_k A[m,k] * B[n,k]   (B always (N x K) row-major)
// Accumulation: strictly ascending k, single accumulator, fmaf — matches
// Eigen gebp / cublas SGEMM rounding.
// AMODE: 0 = A row-major (M x K)
//        1 = A is z (B, DIN, T): A[k][m] = z[b*DIN*T + k*T + t]
//        2 = A rows gathered: row m -> A + gidx[m]*K   (codebook gather)
//        3 = A row-major minus A2 row-major (emb = x - res)
// EPI:   0 = C = acc + bias (row-major, ldc=N); optional duplicate store to C2
//        1 = C -= acc + bias (in-place RMW on residual)
//        2 = transposed store into out tensor (B, DOUT, T) with bias
// ---------------------------------------------------------------------------
template<int AMODE, int EPI>
__global__ void __launch_bounds__(256)
gemm_kernel(const float* __restrict__ A,
            const float* __restrict__ A2,
            const int*   __restrict__ gidx,
            const float* __restrict__ B,
            const float* __restrict__ bias,
            float* __restrict__ C,
            float* __restrict__ C2,
            int K, int N)
{
    __shared__ float As[BK][BM];
    __shared__ float Bs[BK][BN];

    const int tid = threadIdx.x;
    const int m0  = blockIdx.y * BM;
    const int n0  = blockIdx.x * BN;

    const int tx = tid & 15;
    const int ty = tid >> 4;

    const int arow = tid >> 2;          // 0..63
    const int acol = (tid & 3) << 2;    // 0,4,8,12

    const float* aptr0 = nullptr;
    const float* aptr1 = nullptr;
    if constexpr (AMODE == 0 || AMODE == 3) {
        aptr0 = A + (size_t)(m0 + arow) * K;
        aptr1 = A + (size_t)(m0 + arow + 64) * K;
    }
    if constexpr (AMODE == 2) {
        aptr0 = A + (size_t)gidx[m0 + arow] * K;
        aptr1 = A + (size_t)gidx[m0 + arow + 64] * K;
    }
    const float* zb = nullptr;
    int t0z = 0;
    if constexpr (AMODE == 1) {
        const int b = m0 >> 11;             // T=2048 rows per batch, BM|T
        t0z = m0 & (TDIM - 1);
        zb = A + (size_t)b * DIN * TDIM;
    }

    const float* bptr0 = B + (size_t)(n0 + arow) * K;
    const float* bptr1 = B + (size_t)(n0 + arow + 64) * K;

    float acc[8][8];
#pragma unroll
    for (int i = 0; i < 8; ++i)
#pragma unroll
        for (int j = 0; j < 8; ++j) acc[i][j] = 0.f;

    for (int kt = 0; kt < K; kt += BK) {
        if constexpr (AMODE == 1) {
            const int zk = tid >> 5;            // 0..7
            const int zm = (tid & 31) << 2;     // 0..124
#pragma unroll
            for (int it = 0; it < 2; ++it) {
                const int k = zk + it * 8;
                float4 v = *reinterpret_cast<const float4*>(
                    zb + (size_t)(kt + k) * TDIM + t0z + zm);
                *reinterpret_cast<float4*>(&As[k][zm]) = v;
            }
        } else {
            float4 v0 = *reinterpret_cast<const float4*>(aptr0 + kt + acol);
            float4 v1 = *reinterpret_cast<const float4*>(aptr1 + kt + acol);
            if constexpr (AMODE == 3) {
                float4 r0 = *reinterpret_cast<const float4*>(
                    A2 + (size_t)(m0 + arow) * K + kt + acol);
                float4 r1 = *reinterpret_cast<const float4*>(
                    A2 + (size_t)(m0 + arow + 64) * K + kt + acol);
                v0.x = __fsub_rn(v0.x, r0.x); v0.y = __fsub_rn(v0.y, r0.y);
                v0.z = __fsub_rn(v0.z, r0.z); v0.w = __fsub_rn(v0.w, r0.w);
                v1.x = __fsub_rn(v1.x, r1.x); v1.y = __fsub_rn(v1.y, r1.y);
                v1.z = __fsub_rn(v1.z, r1.z); v1.w = __fsub_rn(v1.w, r1.w);
            }
            As[acol + 0][arow] = v0.x;
            As[acol + 1][arow] = v0.y;
            As[acol + 2][arow] = v0.z;
            As[acol + 3][arow] = v0.w;
            As[acol + 0][arow + 64] = v1.x;
            As[acol + 1][arow + 64] = v1.y;
            As[acol + 2][arow + 64] = v1.z;
            As[acol + 3][arow + 64] = v1.w;
        }
        {
            float4 v0 = *reinterpret_cast<const float4*>(bptr0 + kt + acol);
            float4 v1 = *reinterpret_cast<const float4*>(bptr1 + kt + acol);
            Bs[acol + 0][arow] = v0.x;
            Bs[acol + 1][arow] = v0.y;
            Bs[acol + 2][arow] = v0.z;
            Bs[acol + 3][arow] = v0.w;
            Bs[acol + 0][arow + 64] = v1.x;
            Bs[acol + 1][arow + 64] = v1.y;
            Bs[acol + 2][arow + 64] = v1.z;
            Bs[acol + 3][arow + 64] = v1.w;
        }
        __syncthreads();
#pragma unroll
        for (int k = 0; k < BK; ++k) {
            float a[8], bq[8];
            *reinterpret_cast<float4*>(&a[0]) = *reinterpret_cast<const float4*>(&As[k][ty * 4]);
            *reinterpret_cast<float4*>(&a[4]) = *reinterpret_cast<const float4*>(&As[k][64 + ty * 4]);
            *reinterpret_cast<float4*>(&bq[0]) = *reinterpret_cast<const float4*>(&Bs[k][tx * 4]);
            *reinterpret_cast<float4*>(&bq[4]) = *reinterpret_cast<const float4*>(&Bs[k][64 + tx * 4]);
#pragma unroll
            for (int i = 0; i < 8; ++i)
#pragma unroll
                for (int j = 0; j < 8; ++j)
                    acc[i][j] = fmaf(a[i], bq[j], acc[i][j]);
        }
        __syncthreads();
    }

    int rows[8];
#pragma unroll
    for (int i = 0; i < 4; ++i) { rows[i] = ty * 4 + i; rows[i + 4] = 64 + ty * 4 + i; }

    if constexpr (EPI == 0 || EPI == 1) {
#pragma unroll
        for (int i = 0; i < 8; ++i) {
            const size_t r = (size_t)(m0 + rows[i]);
#pragma unroll
            for (int g = 0; g < 2; ++g) {
                const int c = n0 + (g ? 64 : 0) + tx * 4;
                const float4 bv = *reinterpret_cast<const float4*>(bias + c);
                float4 v;
                v.x = __fadd_rn(acc[i][g * 4 + 0], bv.x);
                v.y = __fadd_rn(acc[i][g * 4 + 1], bv.y);
                v.z = __fadd_rn(acc[i][g * 4 + 2], bv.z);
                v.w = __fadd_rn(acc[i][g * 4 + 3], bv.w);
                if constexpr (EPI == 0) {
                    *reinterpret_cast<float4*>(C + r * N + c) = v;
                    if (C2) *reinterpret_cast<float4*>(C2 + r * N + c) = v;
                } else {
                    float4 old = *reinterpret_cast<const float4*>(C + r * N + c);
                    old.x = __fsub_rn(old.x, v.x);
                    old.y = __fsub_rn(old.y, v.y);
                    old.z = __fsub_rn(old.z, v.z);
                    old.w = __fsub_rn(old.w, v.w);
                    *reinterpret_cast<float4*>(C + r * N + c) = old;
                }
            }
        }
    }

    if constexpr (EPI == 2) {
        __shared__ float Cs[32][BM + 4];
        const int b   = m0 >> 11;
        const int t0e = m0 & (TDIM - 1);
#pragma unroll
        for (int s = 0; s < 4; ++s) {
            const int g = s >> 1;
            if ((tx >> 3) == (s & 1)) {
                const int cl = tx * 4 - 32 * (s & 1);
#pragma unroll
                for (int i = 0; i < 8; ++i)
#pragma unroll
                    for (int jj = 0; jj < 4; ++jj)
                        Cs[cl + jj][rows[i]] = acc[i][g * 4 + jj];
            }
            __syncthreads();
            for (int w = tid; w < 32 * BM; w += 256) {
                const int nl = w >> 7;
                const int tl = w & 127;
                const int n  = n0 + s * 32 + nl;
                C[((size_t)b * DOUT + n) * TDIM + t0e + tl] =
                    __fadd_rn(Cs[nl][tl], bias[n]);
            }
            __syncthreads();
        }
    }
}

// ---------------------------------------------------------------------------
// Row squared-norm, sequential-ascending scalar mul+add (matches XLA:CPU
// scalar row reduce rounding). One row per thread, smem-staged for coalescing.
// ROWS_PER_BLOCK=32, 256 threads: coalesced load, 32 threads reduce.
// ---------------------------------------------------------------------------
__global__ void __launch_bounds__(256)
rownorm2_kernel(const float* __restrict__ X, float* __restrict__ out, int nrows)
{
    __shared__ float s[32][CDn + 1];
    const int tid = threadIdx.x;
    const int r0  = blockIdx.x * 32;
    for (int i = tid; i < 32 * CDn; i += 256) {
        const int t = i >> 8;          // row within block
        const int c = i & (CDn - 1);
        s[t][c] = X[(size_t)(r0 + t) * CDn + c];
    }
    __syncthreads();
    if (tid < 32 && r0 + tid < nrows) {
        float acc = 0.f;
#pragma unroll 4
        for (int c = 0; c < CDn; ++c) {
            const float v = s[tid][c];
            acc = __fadd_rn(acc, __fmul_rn(v, v));
        }
        out[r0 + tid] = acc;
    }
}

// ---------------------------------------------------------------------------
// fused distance GEMM + argmin, replicating reference rounding:
//   d = fadd( fsub( enc2, fmul(2, dot) ), cbn )
// Tie-break: lowest index (matches jnp.argmin).
// ---------------------------------------------------------------------------
__global__ void __launch_bounds__(256)
dist_argmin_kernel(const float* __restrict__ enc,
                   const float* __restrict__ enc2,
                   const float* __restrict__ cb,
                   const float* __restrict__ cbn,
                   int* __restrict__ idxOut,
                   float* __restrict__ idxFloat)
{
    __shared__ float As[BK][BM];
    __shared__ float Bs[BK][BN];

    const int tid = threadIdx.x;
    const int m0  = blockIdx.x * BM;
    const int tx  = tid & 15;
    const int ty  = tid >> 4;
    const int arow = tid >> 2;
    const int acol = (tid & 3) << 2;

    const float* aptr0 = enc + (size_t)(m0 + arow) * CDn;
    const float* aptr1 = enc + (size_t)(m0 + arow + 64) * CDn;

    float bestv[8];
    int   besti[8];
#pragma unroll
    for (int i = 0; i < 8; ++i) { bestv[i] = FLT_MAX; besti[i] = 0; }

    int rows[8];
    float e2[8];
#pragma unroll
    for (int i = 0; i < 4; ++i) { rows[i] = ty * 4 + i; rows[i + 4] = 64 + ty * 4 + i; }
#pragma unroll
    for (int i = 0; i < 8; ++i) e2[i] = enc2[m0 + rows[i]];

    for (int n0 = 0; n0 < CSn; n0 += BN) {
        float acc[8][8];
#pragma unroll
        for (int i = 0; i < 8; ++i)
#pragma unroll
            for (int j = 0; j < 8; ++j) acc[i][j] = 0.f;

        const float* bptr0 = cb + (size_t)(n0 + arow) * CDn;
        const float* bptr1 = cb + (size_t)(n0 + arow + 64) * CDn;

        for (int kt = 0; kt < CDn; kt += BK) {
            float4 v0 = *reinterpret_cast<const float4*>(aptr0 + kt + acol);
            float4 v1 = *reinterpret_cast<const float4*>(aptr1 + kt + acol);
            As[acol + 0][arow] = v0.x;
            As[acol + 1][arow] = v0.y;
            As[acol + 2][arow] = v0.z;
            As[acol + 3][arow] = v0.w;
            As[acol + 0][arow + 64] = v1.x;
            As[acol + 1][arow + 64] = v1.y;
            As[acol + 2][arow + 64] = v1.z;
            As[acol + 3][arow + 64] = v1.w;
            float4 w0 = *reinterpret_cast<const float4*>(bptr0 + kt + acol);
            float4 w1 = *reinterpret_cast<const float4*>(bptr1 + kt + acol);
            Bs[acol + 0][arow] = w0.x;
            Bs[acol + 1][arow] = w0.y;
            Bs[acol + 2][arow] = w0.z;
            Bs[acol + 3][arow] = w0.w;
            Bs[acol + 0][arow + 64] = w1.x;
            Bs[acol + 1][arow + 64] = w1.y;
            Bs[acol + 2][arow + 64] = w1.z;
            Bs[acol + 3][arow + 64] = w1.w;
            __syncthreads();
#pragma unroll
            for (int k = 0; k < BK; ++k) {
                float a[8], bq[8];
                *reinterpret_cast<float4*>(&a[0]) = *reinterpret_cast<const float4*>(&As[k][ty * 4]);
                *reinterpret_cast<float4*>(&a[4]) = *reinterpret_cast<const float4*>(&As[k][64 + ty * 4]);
                *reinterpret_cast<float4*>(&bq[0]) = *reinterpret_cast<const float4*>(&Bs[k][tx * 4]);
                *reinterpret_cast<float4*>(&bq[4]) = *reinterpret_cast<const float4*>(&Bs[k][64 + tx * 4]);
#pragma unroll
                for (int i = 0; i < 8; ++i)
#pragma unroll
                    for (int j = 0; j < 8; ++j)
                        acc[i][j] = fmaf(a[i], bq[j], acc[i][j]);
            }
            __syncthreads();
        }
#pragma unroll
        for (int j = 0; j < 8; ++j) {
            const int c = n0 + ((j < 4) ? (tx * 4 + j) : (64 + tx * 4 + j - 4));
            const float cn = cbn[c];
#pragma unroll
            for (int i = 0; i < 8; ++i) {
                // exact reference rounding sequence, contraction-proof
                const float d = __fadd_rn(
                    __fsub_rn(e2[i], __fmul_rn(2.0f, acc[i][j])), cn);
                if (d < bestv[i]) { bestv[i] = d; besti[i] = c; }
            }
        }
    }

    __syncthreads();
    float* redv = &As[0][0];            // 2048 floats
    int*   redi = reinterpret_cast<int*>(&Bs[0][0]);
#pragma unroll
    for (int i = 0; i < 8; ++i) {
        redv[rows[i] * 16 + tx] = bestv[i];
        redi[rows[i] * 16 + tx] = besti[i];
    }
    __syncthreads();
    if (tid < BM) {
        float bv = redv[tid * 16];
        int   bi = redi[tid * 16];
#pragma unroll
        for (int t = 1; t < 16; ++t) {
            const float v = redv[tid * 16 + t];
            const int  ii = redi[tid * 16 + t];
            if (v < bv || (v == bv && ii < bi)) { bv = v; bi = ii; }
        }
        idxOut[m0 + tid] = bi;
        if (idxFloat) idxFloat[m0 + tid] = (float)bi;
    }
}

// ---------------------------------------------------------------------------
// host launcher
// ---------------------------------------------------------------------------
extern "C" void kernel_launch(void* const* d_in, const int* in_sizes, int n_in,
                              void* d_out, int out_size)
{
    const float* z   = (const float*)d_in[0];   // (8, 768, 2048)
    const float* ipw = (const float*)d_in[1];   // (512, 768)
    const float* ipb = (const float*)d_in[2];   // (512,)
    const float* inw = (const float*)d_in[3];   // (8, 256, 512)
    const float* inb = (const float*)d_in[4];   // (8, 256)
    const float* cbk = (const float*)d_in[5];   // (8, 1024, 256)
    const float* oww = (const float*)d_in[6];   // (8, 512, 256)
    const float* owb = (const float*)d_in[7];   // (8, 512)
    const float* opw = (const float*)d_in[8];   // (768, 512)
    const float* opb = (const float*)d_in[9];   // (768,)
    float* outF = (float*)d_out;

    float *gx, *gres, *genc, *genc2, *gcbn;
    int* gidx;
    cudaGetSymbolAddress((void**)&gx,    g_x);
    cudaGetSymbolAddress((void**)&gres,  g_res);
    cudaGetSymbolAddress((void**)&genc,  g_enc);
    cudaGetSymbolAddress((void**)&genc2, g_enc2);
    cudaGetSymbolAddress((void**)&gcbn,  g_cbn);
    cudaGetSymbolAddress((void**)&gidx,  g_idx);

    const dim3 blk(256);
    const long long OUT0 = (long long)8 * DOUT * TDIM;         // 12,582,912
    const bool writeIdx = (long long)out_size >= OUT0 + (long long)NQn * MTOK;

    // 1. input projection: x (and residual copy)
    gemm_kernel<1, 0><<<dim3(RVQn / BN, MTOK / BM), blk>>>(
        z, nullptr, nullptr, ipw, ipb, gx, gres, DIN, RVQn);

    // 2. RVQ stages
    for (int q = 0; q < NQn; ++q) {
        const float* cbq = cbk + (size_t)q * CSn * CDn;
        rownorm2_kernel<<<CSn / 32, 256>>>(cbq, gcbn, CSn);
        gemm_kernel<0, 0><<<dim3(CDn / BN, MTOK / BM), blk>>>(
            gres, nullptr, nullptr,
            inw + (size_t)q * CDn * RVQn, inb + (size_t)q * CDn,
            genc, nullptr, RVQn, CDn);
        rownorm2_kernel<<<MTOK / 32, 256>>>(genc, genc2, MTOK);
        float* idxF = writeIdx ? (outF + OUT0 + (size_t)q * MTOK) : nullptr;
        dist_argmin_kernel<<<MTOK / BM, blk>>>(genc, genc2, cbq, gcbn, gidx, idxF);
        gemm_kernel<2, 1><<<dim3(RVQn / BN, MTOK / BM), blk>>>(
            cbq, nullptr, gidx,
            oww + (size_t)q * RVQn * CDn, owb + (size_t)q * RVQn,
            gres, nullptr, CDn, RVQn);
    }

    // 3. output projection on emb = x - res, transposed store into (B, 768, T)
    gemm_kernel<3, 2><<<dim3(DOUT / BN, MTOK / BM), blk>>>(
        gx, gres, nullptr, opw, opb, outF, nullptr, RVQn, DOUT);
}

// round 8
// speedup vs baseline: 1.1414x; 1.1414x over previous
#include <cuda_runtime.h>
#include <cfloat>

// ---------------------------------------------------------------------------
// ResidualVQ on GB300 — round 3: exact-fp32 pipeline, now with
//   * double-buffered smem GEMMs (1 sync per k-tile, ldg/compute overlap)
//   * dist/argmin split over 8 code chunks (1024 CTAs) + exact reduce pass
//   * faster rownorm2 (256 rows/block)
// Numerics identical to the passing round-2 kernel: ascending-k single-acc
// fma GEMMs, sequential scalar row norms, d = fadd(fsub(enc2, fmul(2,dot)), cbn).
// ---------------------------------------------------------------------------

#define BM 128
#define BN 128
#define BK 16

#define MTOK 16384
#define TDIM 2048
#define DIN  768
#define RVQn 512
#define NQn  8
#define CSn  1024
#define CDn  256
#define DOUT 768

// scratch (device globals; no allocation allowed)
__device__ float g_x   [MTOK * RVQn];
__device__ float g_res [MTOK * RVQn];
__device__ float g_enc [MTOK * CDn];
__device__ float g_enc2[MTOK];
__device__ float g_cbn [CSn];
__device__ int   g_idx [MTOK];
__device__ float g_pbv [8 * MTOK];     // per-chunk partial best value
__device__ int   g_pbi [8 * MTOK];     // per-chunk partial best index

// shared-memory pool indexing (single array so the epilogue can reuse it)
#define AS(b,k,m) SM[(b)*(BK*BM) + (k)*BM + (m)]
#define BS(b,k,n) SM[2*(BK*BM) + (b)*(BK*BN) + (k)*BN + (n)]

// ---------------------------------------------------------------------------
// Unified SGEMM: C[m,n] = sum_k A[m,k] * B[n,k]   (B always (N x K) row-major)
// AMODE: 0 = A row-major; 1 = A is z (B,DIN,T) transposed view;
//        2 = A rows gathered via gidx; 3 = A - A2 row-major.
// EPI:   0 = C = acc + bias (+ optional dup store C2)
//        1 = C -= acc + bias (residual RMW)
//        2 = transposed store into (B, DOUT, T) with bias
// ---------------------------------------------------------------------------
template<int AMODE, int EPI>
__global__ void __launch_bounds__(256, 2)
gemm_kernel(const float* __restrict__ A,
            const float* __restrict__ A2,
            const int*   __restrict__ gidx,
            const float* __restrict__ B,
            const float* __restrict__ bias,
            float* __restrict__ C,
            float* __restrict__ C2,
            int K, int N)
{
    __shared__ float SM[2*BK*BM + 2*BK*BN];   // 32 KB

    const int tid = threadIdx.x;
    const int m0  = blockIdx.y * BM;
    const int n0  = blockIdx.x * BN;

    const int tx = tid & 15;
    const int ty = tid >> 4;

    const int arow = tid >> 2;          // 0..63
    const int acol = (tid & 3) << 2;    // 0,4,8,12

    const float* aptr0 = nullptr;
    const float* aptr1 = nullptr;
    if constexpr (AMODE == 0 || AMODE == 3) {
        aptr0 = A + (size_t)(m0 + arow) * K;
        aptr1 = A + (size_t)(m0 + arow + 64) * K;
    }
    if constexpr (AMODE == 2) {
        aptr0 = A + (size_t)gidx[m0 + arow] * K;
        aptr1 = A + (size_t)gidx[m0 + arow + 64] * K;
    }
    const float* zb = nullptr;
    int t0z = 0, zk = 0, zm = 0;
    if constexpr (AMODE == 1) {
        const int b = m0 >> 11;
        t0z = m0 & (TDIM - 1);
        zb  = A + (size_t)b * DIN * TDIM;
        zk  = tid >> 5;
        zm  = (tid & 31) << 2;
    }
    const float* bptr0 = B + (size_t)(n0 + arow) * K;
    const float* bptr1 = B + (size_t)(n0 + arow + 64) * K;

    float4 ra0, ra1, rb0, rb1;

    auto load_tile = [&](int kt) {
        const int k0 = kt * BK;
        if constexpr (AMODE == 1) {
            ra0 = *reinterpret_cast<const float4*>(zb + (size_t)(k0 + zk)     * TDIM + t0z + zm);
            ra1 = *reinterpret_cast<const float4*>(zb + (size_t)(k0 + zk + 8) * TDIM + t0z + zm);
        } else {
            ra0 = *reinterpret_cast<const float4*>(aptr0 + k0 + acol);
            ra1 = *reinterpret_cast<const float4*>(aptr1 + k0 + acol);
            if constexpr (AMODE == 3) {
                float4 r0 = *reinterpret_cast<const float4*>(A2 + (size_t)(m0 + arow)      * K + k0 + acol);
                float4 r1 = *reinterpret_cast<const float4*>(A2 + (size_t)(m0 + arow + 64) * K + k0 + acol);
                ra0.x = __fsub_rn(ra0.x, r0.x); ra0.y = __fsub_rn(ra0.y, r0.y);
                ra0.z = __fsub_rn(ra0.z, r0.z); ra0.w = __fsub_rn(ra0.w, r0.w);
                ra1.x = __fsub_rn(ra1.x, r1.x); ra1.y = __fsub_rn(ra1.y, r1.y);
                ra1.z = __fsub_rn(ra1.z, r1.z); ra1.w = __fsub_rn(ra1.w, r1.w);
            }
        }
        rb0 = *reinterpret_cast<const float4*>(bptr0 + k0 + acol);
        rb1 = *reinterpret_cast<const float4*>(bptr1 + k0 + acol);
    };

    auto store_tile = [&](int b) {
        if constexpr (AMODE == 1) {
            *reinterpret_cast<float4*>(&AS(b, zk,     zm)) = ra0;
            *reinterpret_cast<float4*>(&AS(b, zk + 8, zm)) = ra1;
        } else {
            AS(b, acol + 0, arow) = ra0.x;
            AS(b, acol + 1, arow) = ra0.y;
            AS(b, acol + 2, arow) = ra0.z;
            AS(b, acol + 3, arow) = ra0.w;
            AS(b, acol + 0, arow + 64) = ra1.x;
            AS(b, acol + 1, arow + 64) = ra1.y;
            AS(b, acol + 2, arow + 64) = ra1.z;
            AS(b, acol + 3, arow + 64) = ra1.w;
        }
        BS(b, acol + 0, arow) = rb0.x;
        BS(b, acol + 1, arow) = rb0.y;
        BS(b, acol + 2, arow) = rb0.z;
        BS(b, acol + 3, arow) = rb0.w;
        BS(b, acol + 0, arow + 64) = rb1.x;
        BS(b, acol + 1, arow + 64) = rb1.y;
        BS(b, acol + 2, arow + 64) = rb1.z;
        BS(b, acol + 3, arow + 64) = rb1.w;
    };

    float acc[8][8];
#pragma unroll
    for (int i = 0; i < 8; ++i)
#pragma unroll
        for (int j = 0; j < 8; ++j) acc[i][j] = 0.f;

    auto compute = [&](int b) {
#pragma unroll
        for (int k = 0; k < BK; ++k) {
            float a[8], bq[8];
            *reinterpret_cast<float4*>(&a[0])  = *reinterpret_cast<const float4*>(&AS(b, k, ty * 4));
            *reinterpret_cast<float4*>(&a[4])  = *reinterpret_cast<const float4*>(&AS(b, k, 64 + ty * 4));
            *reinterpret_cast<float4*>(&bq[0]) = *reinterpret_cast<const float4*>(&BS(b, k, tx * 4));
            *reinterpret_cast<float4*>(&bq[4]) = *reinterpret_cast<const float4*>(&BS(b, k, 64 + tx * 4));
#pragma unroll
            for (int i = 0; i < 8; ++i)
#pragma unroll
                for (int j = 0; j < 8; ++j)
                    acc[i][j] = fmaf(a[i], bq[j], acc[i][j]);
        }
    };

    const int ntiles = K / BK;
    load_tile(0);
    store_tile(0);
    __syncthreads();
    int buf = 0;
    for (int kt = 0; kt < ntiles; ++kt) {
        const bool has_next = (kt + 1 < ntiles);
        if (has_next) load_tile(kt + 1);
        compute(buf);
        if (has_next) {
            store_tile(buf ^ 1);
            __syncthreads();
            buf ^= 1;
        }
    }

    int rows[8];
#pragma unroll
    for (int i = 0; i < 4; ++i) { rows[i] = ty * 4 + i; rows[i + 4] = 64 + ty * 4 + i; }

    if constexpr (EPI == 0 || EPI == 1) {
#pragma unroll
        for (int i = 0; i < 8; ++i) {
            const size_t r = (size_t)(m0 + rows[i]);
#pragma unroll
            for (int g = 0; g < 2; ++g) {
                const int c = n0 + (g ? 64 : 0) + tx * 4;
                const float4 bv = *reinterpret_cast<const float4*>(bias + c);
                float4 v;
                v.x = __fadd_rn(acc[i][g * 4 + 0], bv.x);
                v.y = __fadd_rn(acc[i][g * 4 + 1], bv.y);
                v.z = __fadd_rn(acc[i][g * 4 + 2], bv.z);
                v.w = __fadd_rn(acc[i][g * 4 + 3], bv.w);
                if constexpr (EPI == 0) {
                    *reinterpret_cast<float4*>(C + r * N + c) = v;
                    if (C2) *reinterpret_cast<float4*>(C2 + r * N + c) = v;
                } else {
                    float4 old = *reinterpret_cast<const float4*>(C + r * N + c);
                    old.x = __fsub_rn(old.x, v.x);
                    old.y = __fsub_rn(old.y, v.y);
                    old.z = __fsub_rn(old.z, v.z);
                    old.w = __fsub_rn(old.w, v.w);
                    *reinterpret_cast<float4*>(C + r * N + c) = old;
                }
            }
        }
    }

    if constexpr (EPI == 2) {
        // transposed store via 32-col smem slices; reuse SM pool (>= 4224 floats)
        float* Cs = &SM[0];                      // [32][BM+4]
        const int b   = m0 >> 11;
        const int t0e = m0 & (TDIM - 1);
        __syncthreads();
#pragma unroll
        for (int s = 0; s < 4; ++s) {
            const int g = s >> 1;
            if ((tx >> 3) == (s & 1)) {
                const int cl = tx * 4 - 32 * (s & 1);
#pragma unroll
                for (int i = 0; i < 8; ++i)
#pragma unroll
                    for (int jj = 0; jj < 4; ++jj)
                        Cs[(cl + jj) * (BM + 4) + rows[i]] = acc[i][g * 4 + jj];
            }
            __syncthreads();
            for (int w = tid; w < 32 * BM; w += 256) {
                const int nl = w >> 7;
                const int tl = w & 127;
                const int n  = n0 + s * 32 + nl;
                C[((size_t)b * DOUT + n) * TDIM + t0e + tl] =
                    __fadd_rn(Cs[nl * (BM + 4) + tl], bias[n]);
            }
            __syncthreads();
        }
    }
}

// ---------------------------------------------------------------------------
// Row squared-norm, sequential-ascending scalar mul+add.
// 256 rows per block, staged in 32-col chunks (conflict-free smem).
// ---------------------------------------------------------------------------
__global__ void __launch_bounds__(256)
rownorm2_kernel(const float* __restrict__ X, float* __restrict__ out, int nrows)
{
    __shared__ float s[256][33];
    const int tid = threadIdx.x;
    const int r0  = blockIdx.x * 256;
    float acc = 0.f;
    for (int c0 = 0; c0 < CDn; c0 += 32) {
        for (int i = tid; i < 256 * 32; i += 256) {
            const int r = i >> 5, c = i & 31;
            s[r][c] = X[(size_t)(r0 + r) * CDn + c0 + c];
        }
        __syncthreads();
#pragma unroll
        for (int c = 0; c < 32; ++c) {
            const float v = s[tid][c];
            acc = __fadd_rn(acc, __fmul_rn(v, v));
        }
        __syncthreads();
    }
    if (r0 + tid < nrows) out[r0 + tid] = acc;
}

// ---------------------------------------------------------------------------
// dist partial: one CTA = (128-token m-tile) x (128-code chunk). Double-buffered
// GEMM over K=256, then per-chunk argmin partial to g_pbv/g_pbi.
//   d = fadd( fsub( enc2, fmul(2, dot) ), cbn )   — exact reference rounding.
// ---------------------------------------------------------------------------
__global__ void __launch_bounds__(256, 2)
dist_partial_kernel(const float* __restrict__ enc,
                    const float* __restrict__ enc2,
                    const float* __restrict__ cb,
                    const float* __restrict__ cbn,
                    float* __restrict__ pbv,
                    int*   __restrict__ pbi)
{
    __shared__ float SM[2*BK*BM + 2*BK*BN];

    const int tid   = threadIdx.x;
    const int m0    = blockIdx.x * BM;
    const int chunk = blockIdx.y;
    const int n0    = chunk * BN;

    const int tx = tid & 15;
    const int ty = tid >> 4;
    const int arow = tid >> 2;
    const int acol = (tid & 3) << 2;

    const float* aptr0 = enc + (size_t)(m0 + arow) * CDn;
    const float* aptr1 = enc + (size_t)(m0 + arow + 64) * CDn;
    const float* bptr0 = cb + (size_t)(n0 + arow) * CDn;
    const float* bptr1 = cb + (size_t)(n0 + arow + 64) * CDn;

    float4 ra0, ra1, rb0, rb1;
    auto load_tile = [&](int kt) {
        const int k0 = kt * BK;
        ra0 = *reinterpret_cast<const float4*>(aptr0 + k0 + acol);
        ra1 = *reinterpret_cast<const float4*>(aptr1 + k0 + acol);
        rb0 = *reinterpret_cast<const float4*>(bptr0 + k0 + acol);
        rb1 = *reinterpret_cast<const float4*>(bptr1 + k0 + acol);
    };
    auto store_tile = [&](int b) {
        AS(b, acol + 0, arow) = ra0.x;
        AS(b, acol + 1, arow) = ra0.y;
        AS(b, acol + 2, arow) = ra0.z;
        AS(b, acol + 3, arow) = ra0.w;
        AS(b, acol + 0, arow + 64) = ra1.x;
        AS(b, acol + 1, arow + 64) = ra1.y;
        AS(b, acol + 2, arow + 64) = ra1.z;
        AS(b, acol + 3, arow + 64) = ra1.w;
        BS(b, acol + 0, arow) = rb0.x;
        BS(b, acol + 1, arow) = rb0.y;
        BS(b, acol + 2, arow) = rb0.z;
        BS(b, acol + 3, arow) = rb0.w;
        BS(b, acol + 0, arow + 64) = rb1.x;
        BS(b, acol + 1, arow + 64) = rb1.y;
        BS(b, acol + 2, arow + 64) = rb1.z;
        BS(b, acol + 3, arow + 64) = rb1.w;
    };

    float acc[8][8];
#pragma unroll
    for (int i = 0; i < 8; ++i)
#pragma unroll
        for (int j = 0; j < 8; ++j) acc[i][j] = 0.f;

    const int ntiles = CDn / BK;        // 16
    load_tile(0);
    store_tile(0);
    __syncthreads();
    int buf = 0;
    for (int kt = 0; kt < ntiles; ++kt) {
        const bool has_next = (kt + 1 < ntiles);
        if (has_next) load_tile(kt + 1);
#pragma unroll
        for (int k = 0; k < BK; ++k) {
            float a[8], bq[8];
            *reinterpret_cast<float4*>(&a[0])  = *reinterpret_cast<const float4*>(&AS(buf, k, ty * 4));
            *reinterpret_cast<float4*>(&a[4])  = *reinterpret_cast<const float4*>(&AS(buf, k, 64 + ty * 4));
            *reinterpret_cast<float4*>(&bq[0]) = *reinterpret_cast<const float4*>(&BS(buf, k, tx * 4));
            *reinterpret_cast<float4*>(&bq[4]) = *reinterpret_cast<const float4*>(&BS(buf, k, 64 + tx * 4));
#pragma unroll
            for (int i = 0; i < 8; ++i)
#pragma unroll
                for (int j = 0; j < 8; ++j)
                    acc[i][j] = fmaf(a[i], bq[j], acc[i][j]);
        }
        if (has_next) {
            store_tile(buf ^ 1);
            __syncthreads();
            buf ^= 1;
        }
    }

    int rows[8];
    float e2[8];
#pragma unroll
    for (int i = 0; i < 4; ++i) { rows[i] = ty * 4 + i; rows[i + 4] = 64 + ty * 4 + i; }
#pragma unroll
    for (int i = 0; i < 8; ++i) e2[i] = enc2[m0 + rows[i]];

    float bestv[8];
    int   besti[8];
#pragma unroll
    for (int i = 0; i < 8; ++i) { bestv[i] = FLT_MAX; besti[i] = 0; }

#pragma unroll
    for (int j = 0; j < 8; ++j) {
        const int c = n0 + ((j < 4) ? (tx * 4 + j) : (64 + tx * 4 + j - 4));
        const float cn = cbn[c];
#pragma unroll
        for (int i = 0; i < 8; ++i) {
            const float d = __fadd_rn(
                __fsub_rn(e2[i], __fmul_rn(2.0f, acc[i][j])), cn);
            if (d < bestv[i] || (d == bestv[i] && c < besti[i])) {
                bestv[i] = d; besti[i] = c;
            }
        }
    }

    // cross-thread reduction (16 tx-threads per token row) via SM pool
    __syncthreads();
    float* redv = &SM[0];                          // 2048 floats
    int*   redi = reinterpret_cast<int*>(&SM[2048]);
#pragma unroll
    for (int i = 0; i < 8; ++i) {
        redv[rows[i] * 16 + tx] = bestv[i];
        redi[rows[i] * 16 + tx] = besti[i];
    }
    __syncthreads();
    if (tid < BM) {
        float bv = redv[tid * 16];
        int   bi = redi[tid * 16];
#pragma unroll
        for (int t = 1; t < 16; ++t) {
            const float v = redv[tid * 16 + t];
            const int  ii = redi[tid * 16 + t];
            if (v < bv || (v == bv && ii < bi)) { bv = v; bi = ii; }
        }
        pbv[(size_t)chunk * MTOK + m0 + tid] = bv;
        pbi[(size_t)chunk * MTOK + m0 + tid] = bi;
    }
}

// ---------------------------------------------------------------------------
// final argmin over 8 chunk partials (exact lowest-index tie-break)
// ---------------------------------------------------------------------------
__global__ void __launch_bounds__(256)
argmin_reduce_kernel(const float* __restrict__ pbv,
                     const int*   __restrict__ pbi,
                     int* __restrict__ idxOut,
                     float* __restrict__ idxFloat)
{
    const int m = blockIdx.x * 256 + threadIdx.x;
    float bv = pbv[m];
    int   bi = pbi[m];
#pragma unroll
    for (int c = 1; c < 8; ++c) {
        const float v = pbv[(size_t)c * MTOK + m];
        const int  ii = pbi[(size_t)c * MTOK + m];
        if (v < bv || (v == bv && ii < bi)) { bv = v; bi = ii; }
    }
    idxOut[m] = bi;
    if (idxFloat) idxFloat[m] = (float)bi;
}

// ---------------------------------------------------------------------------
// host launcher
// ---------------------------------------------------------------------------
extern "C" void kernel_launch(void* const* d_in, const int* in_sizes, int n_in,
                              void* d_out, int out_size)
{
    const float* z   = (const float*)d_in[0];
    const float* ipw = (const float*)d_in[1];
    const float* ipb = (const float*)d_in[2];
    const float* inw = (const float*)d_in[3];
    const float* inb = (const float*)d_in[4];
    const float* cbk = (const float*)d_in[5];
    const float* oww = (const float*)d_in[6];
    const float* owb = (const float*)d_in[7];
    const float* opw = (const float*)d_in[8];
    const float* opb = (const float*)d_in[9];
    float* outF = (float*)d_out;

    float *gx, *gres, *genc, *genc2, *gcbn, *gpbv;
    int *gidx, *gpbi;
    cudaGetSymbolAddress((void**)&gx,    g_x);
    cudaGetSymbolAddress((void**)&gres,  g_res);
    cudaGetSymbolAddress((void**)&genc,  g_enc);
    cudaGetSymbolAddress((void**)&genc2, g_enc2);
    cudaGetSymbolAddress((void**)&gcbn,  g_cbn);
    cudaGetSymbolAddress((void**)&gidx,  g_idx);
    cudaGetSymbolAddress((void**)&gpbv,  g_pbv);
    cudaGetSymbolAddress((void**)&gpbi,  g_pbi);

    const dim3 blk(256);
    const long long OUT0 = (long long)8 * DOUT * TDIM;
    const bool writeIdx = (long long)out_size >= OUT0 + (long long)NQn * MTOK;

    // 1. input projection: x (and residual copy)
    gemm_kernel<1, 0><<<dim3(RVQn / BN, MTOK / BM), blk>>>(
        z, nullptr, nullptr, ipw, ipb, gx, gres, DIN, RVQn);

    // 2. RVQ stages
    for (int q = 0; q < NQn; ++q) {
        const float* cbq = cbk + (size_t)q * CSn * CDn;
        rownorm2_kernel<<<CSn / 256, 256>>>(cbq, gcbn, CSn);
        gemm_kernel<0, 0><<<dim3(CDn / BN, MTOK / BM), blk>>>(
            gres, nullptr, nullptr,
            inw + (size_t)q * CDn * RVQn, inb + (size_t)q * CDn,
            genc, nullptr, RVQn, CDn);
        rownorm2_kernel<<<MTOK / 256, 256>>>(genc, genc2, MTOK);
        dist_partial_kernel<<<dim3(MTOK / BM, CSn / BN), blk>>>(
            genc, genc2, cbq, gcbn, gpbv, gpbi);
        float* idxF = writeIdx ? (outF + OUT0 + (size_t)q * MTOK) : nullptr;
        argmin_reduce_kernel<<<MTOK / 256, 256>>>(gpbv, gpbi, gidx, idxF);
        gemm_kernel<2, 1><<<dim3(RVQn / BN, MTOK / BM), blk>>>(
            cbq, nullptr, gidx,
            oww + (size_t)q * RVQn * CDn, owb + (size_t)q * RVQn,
            gres, nullptr, CDn, RVQn);
    }

    // 3. output projection on emb = x - res, transposed store
    gemm_kernel<3, 2><<<dim3(DOUT / BN, MTOK / BM), blk>>>(
        gx, gres, nullptr, opw, opb, outF, nullptr, RVQn, DOUT);
}

// round 9
// speedup vs baseline: 1.3000x; 1.1390x over previous
#include <cuda_runtime.h>
#include <cfloat>

// ---------------------------------------------------------------------------
// ResidualVQ on GB300 — round 4: exact-fp32 pipeline.
//   * all codebook norms hoisted to ONE up-front launch (outside stage loop)
//   * ||enc||^2 fused into dist_partial (ascending-order scalar sum preserved)
//   * double-buffered smem GEMMs, dist split over 8 code chunks (1024 CTAs)
// Numerics identical to passing kernels: ascending-k single-acc fma GEMMs,
// sequential scalar row norms, d = fadd(fsub(enc2, fmul(2,dot)), cbn).
// ---------------------------------------------------------------------------

#define BM 128
#define BN 128
#define BK 16

#define MTOK 16384
#define TDIM 2048
#define DIN  768
#define RVQn 512
#define NQn  8
#define CSn  1024
#define CDn  256
#define DOUT 768

// scratch (device globals; no allocation allowed)
__device__ float g_x   [MTOK * RVQn];
__device__ float g_res [MTOK * RVQn];
__device__ float g_enc [MTOK * CDn];
__device__ float g_cbn [NQn * CSn];    // all-stage codebook norms
__device__ int   g_idx [MTOK];
__device__ float g_pbv [8 * MTOK];     // per-chunk partial best value
__device__ int   g_pbi [8 * MTOK];     // per-chunk partial best index

// shared-memory pool indexing
#define AS(b,k,m) SM[(b)*(BK*BM) + (k)*BM + (m)]
#define BS(b,k,n) SM[2*(BK*BM) + (b)*(BK*BN) + (k)*BN + (n)]

// ---------------------------------------------------------------------------
// Unified SGEMM: C[m,n] = sum_k A[m,k] * B[n,k]   (B always (N x K) row-major)
// AMODE: 0 = A row-major; 1 = A is z (B,DIN,T) transposed view;
//        2 = A rows gathered via gidx; 3 = A - A2 row-major.
// EPI:   0 = C = acc + bias (+ optional dup store C2)
//        1 = C -= acc + bias (residual RMW)
//        2 = transposed store into (B, DOUT, T) with bias
// ---------------------------------------------------------------------------
template<int AMODE, int EPI>
__global__ void __launch_bounds__(256, 2)
gemm_kernel(const float* __restrict__ A,
            const float* __restrict__ A2,
            const int*   __restrict__ gidx,
            const float* __restrict__ B,
            const float* __restrict__ bias,
            float* __restrict__ C,
            float* __restrict__ C2,
            int K, int N)
{
    __shared__ float SM[2*BK*BM + 2*BK*BN];   // 32 KB

    const int tid = threadIdx.x;
    const int m0  = blockIdx.y * BM;
    const int n0  = blockIdx.x * BN;

    const int tx = tid & 15;
    const int ty = tid >> 4;

    const int arow = tid >> 2;          // 0..63
    const int acol = (tid & 3) << 2;    // 0,4,8,12

    const float* aptr0 = nullptr;
    const float* aptr1 = nullptr;
    if constexpr (AMODE == 0 || AMODE == 3) {
        aptr0 = A + (size_t)(m0 + arow) * K;
        aptr1 = A + (size_t)(m0 + arow + 64) * K;
    }
    if constexpr (AMODE == 2) {
        aptr0 = A + (size_t)gidx[m0 + arow] * K;
        aptr1 = A + (size_t)gidx[m0 + arow + 64] * K;
    }
    const float* zb = nullptr;
    int t0z = 0, zk = 0, zm = 0;
    if constexpr (AMODE == 1) {
        const int b = m0 >> 11;
        t0z = m0 & (TDIM - 1);
        zb  = A + (size_t)b * DIN * TDIM;
        zk  = tid >> 5;
        zm  = (tid & 31) << 2;
    }
    const float* bptr0 = B + (size_t)(n0 + arow) * K;
    const float* bptr1 = B + (size_t)(n0 + arow + 64) * K;

    float4 ra0, ra1, rb0, rb1;

    auto load_tile = [&](int kt) {
        const int k0 = kt * BK;
        if constexpr (AMODE == 1) {
            ra0 = *reinterpret_cast<const float4*>(zb + (size_t)(k0 + zk)     * TDIM + t0z + zm);
            ra1 = *reinterpret_cast<const float4*>(zb + (size_t)(k0 + zk + 8) * TDIM + t0z + zm);
        } else {
            ra0 = *reinterpret_cast<const float4*>(aptr0 + k0 + acol);
            ra1 = *reinterpret_cast<const float4*>(aptr1 + k0 + acol);
            if constexpr (AMODE == 3) {
                float4 r0 = *reinterpret_cast<const float4*>(A2 + (size_t)(m0 + arow)      * K + k0 + acol);
                float4 r1 = *reinterpret_cast<const float4*>(A2 + (size_t)(m0 + arow + 64) * K + k0 + acol);
                ra0.x = __fsub_rn(ra0.x, r0.x); ra0.y = __fsub_rn(ra0.y, r0.y);
                ra0.z = __fsub_rn(ra0.z, r0.z); ra0.w = __fsub_rn(ra0.w, r0.w);
                ra1.x = __fsub_rn(ra1.x, r1.x); ra1.y = __fsub_rn(ra1.y, r1.y);
                ra1.z = __fsub_rn(ra1.z, r1.z); ra1.w = __fsub_rn(ra1.w, r1.w);
            }
        }
        rb0 = *reinterpret_cast<const float4*>(bptr0 + k0 + acol);
        rb1 = *reinterpret_cast<const float4*>(bptr1 + k0 + acol);
    };

    auto store_tile = [&](int b) {
        if constexpr (AMODE == 1) {
            *reinterpret_cast<float4*>(&AS(b, zk,     zm)) = ra0;
            *reinterpret_cast<float4*>(&AS(b, zk + 8, zm)) = ra1;
        } else {
            AS(b, acol + 0, arow) = ra0.x;
            AS(b, acol + 1, arow) = ra0.y;
            AS(b, acol + 2, arow) = ra0.z;
            AS(b, acol + 3, arow) = ra0.w;
            AS(b, acol + 0, arow + 64) = ra1.x;
            AS(b, acol + 1, arow + 64) = ra1.y;
            AS(b, acol + 2, arow + 64) = ra1.z;
            AS(b, acol + 3, arow + 64) = ra1.w;
        }
        BS(b, acol + 0, arow) = rb0.x;
        BS(b, acol + 1, arow) = rb0.y;
        BS(b, acol + 2, arow) = rb0.z;
        BS(b, acol + 3, arow) = rb0.w;
        BS(b, acol + 0, arow + 64) = rb1.x;
        BS(b, acol + 1, arow + 64) = rb1.y;
        BS(b, acol + 2, arow + 64) = rb1.z;
        BS(b, acol + 3, arow + 64) = rb1.w;
    };

    float acc[8][8];
#pragma unroll
    for (int i = 0; i < 8; ++i)
#pragma unroll
        for (int j = 0; j < 8; ++j) acc[i][j] = 0.f;

    auto compute = [&](int b) {
#pragma unroll
        for (int k = 0; k < BK; ++k) {
            float a[8], bq[8];
            *reinterpret_cast<float4*>(&a[0])  = *reinterpret_cast<const float4*>(&AS(b, k, ty * 4));
            *reinterpret_cast<float4*>(&a[4])  = *reinterpret_cast<const float4*>(&AS(b, k, 64 + ty * 4));
            *reinterpret_cast<float4*>(&bq[0]) = *reinterpret_cast<const float4*>(&BS(b, k, tx * 4));
            *reinterpret_cast<float4*>(&bq[4]) = *reinterpret_cast<const float4*>(&BS(b, k, 64 + tx * 4));
#pragma unroll
            for (int i = 0; i < 8; ++i)
#pragma unroll
                for (int j = 0; j < 8; ++j)
                    acc[i][j] = fmaf(a[i], bq[j], acc[i][j]);
        }
    };

    const int ntiles = K / BK;
    load_tile(0);
    store_tile(0);
    __syncthreads();
    int buf = 0;
    for (int kt = 0; kt < ntiles; ++kt) {
        const bool has_next = (kt + 1 < ntiles);
        if (has_next) load_tile(kt + 1);
        compute(buf);
        if (has_next) {
            store_tile(buf ^ 1);
            __syncthreads();
            buf ^= 1;
        }
    }

    int rows[8];
#pragma unroll
    for (int i = 0; i < 4; ++i) { rows[i] = ty * 4 + i; rows[i + 4] = 64 + ty * 4 + i; }

    if constexpr (EPI == 0 || EPI == 1) {
#pragma unroll
        for (int i = 0; i < 8; ++i) {
            const size_t r = (size_t)(m0 + rows[i]);
#pragma unroll
            for (int g = 0; g < 2; ++g) {
                const int c = n0 + (g ? 64 : 0) + tx * 4;
                const float4 bv = *reinterpret_cast<const float4*>(bias + c);
                float4 v;
                v.x = __fadd_rn(acc[i][g * 4 + 0], bv.x);
                v.y = __fadd_rn(acc[i][g * 4 + 1], bv.y);
                v.z = __fadd_rn(acc[i][g * 4 + 2], bv.z);
                v.w = __fadd_rn(acc[i][g * 4 + 3], bv.w);
                if constexpr (EPI == 0) {
                    *reinterpret_cast<float4*>(C + r * N + c) = v;
                    if (C2) *reinterpret_cast<float4*>(C2 + r * N + c) = v;
                } else {
                    float4 old = *reinterpret_cast<const float4*>(C + r * N + c);
                    old.x = __fsub_rn(old.x, v.x);
                    old.y = __fsub_rn(old.y, v.y);
                    old.z = __fsub_rn(old.z, v.z);
                    old.w = __fsub_rn(old.w, v.w);
                    *reinterpret_cast<float4*>(C + r * N + c) = old;
                }
            }
        }
    }

    if constexpr (EPI == 2) {
        float* Cs = &SM[0];                      // [32][BM+4]
        const int b   = m0 >> 11;
        const int t0e = m0 & (TDIM - 1);
        __syncthreads();
#pragma unroll
        for (int s = 0; s < 4; ++s) {
            const int g = s >> 1;
            if ((tx >> 3) == (s & 1)) {
                const int cl = tx * 4 - 32 * (s & 1);
#pragma unroll
                for (int i = 0; i < 8; ++i)
#pragma unroll
                    for (int jj = 0; jj < 4; ++jj)
                        Cs[(cl + jj) * (BM + 4) + rows[i]] = acc[i][g * 4 + jj];
            }
            __syncthreads();
            for (int w = tid; w < 32 * BM; w += 256) {
                const int nl = w >> 7;
                const int tl = w & 127;
                const int n  = n0 + s * 32 + nl;
                C[((size_t)b * DOUT + n) * TDIM + t0e + tl] =
                    __fadd_rn(Cs[nl * (BM + 4) + tl], bias[n]);
            }
            __syncthreads();
        }
    }
}

// ---------------------------------------------------------------------------
// All codebook row norms in one launch: 8*1024 rows of length 256.
// 32 rows/block (grid=256), smem-staged coalesced load, sequential-ascending
// scalar mul+add per row (exact reference rounding).
// ---------------------------------------------------------------------------
__global__ void __launch_bounds__(256)
cbnorm_all_kernel(const float* __restrict__ CB, float* __restrict__ out)
{
    __shared__ float s[32][CDn + 1];
    const int tid = threadIdx.x;
    const int r0  = blockIdx.x * 32;
    for (int i = tid; i < 32 * CDn; i += 256) {
        const int t = i >> 8;
        const int c = i & (CDn - 1);
        s[t][c] = CB[(size_t)(r0 + t) * CDn + c];
    }
    __syncthreads();
    if (tid < 32) {
        float acc = 0.f;
#pragma unroll 8
        for (int c = 0; c < CDn; ++c) {
            const float v = s[tid][c];
            acc = __fadd_rn(acc, __fmul_rn(v, v));
        }
        out[r0 + tid] = acc;
    }
}

// ---------------------------------------------------------------------------
// dist partial with FUSED ||enc||^2: one CTA = (128-token m-tile) x (128-code
// chunk). Threads 0..127 accumulate the sequential-ascending squared row sum
// from the A smem tiles as they stream through (identical rounding to a
// standalone scalar row reduce). Then per-chunk argmin partials.
//   d = fadd( fsub( enc2, fmul(2, dot) ), cbn )
// ---------------------------------------------------------------------------
__global__ void __launch_bounds__(256, 2)
dist_partial_kernel(const float* __restrict__ enc,
                    const float* __restrict__ cb,
                    const float* __restrict__ cbn,
                    float* __restrict__ pbv,
                    int*   __restrict__ pbi)
{
    __shared__ float SM[2*BK*BM + 2*BK*BN];
    __shared__ float e2s[BM];

    const int tid   = threadIdx.x;
    const int m0    = blockIdx.x * BM;
    const int chunk = blockIdx.y;
    const int n0    = chunk * BN;

    const int tx = tid & 15;
    const int ty = tid >> 4;
    const int arow = tid >> 2;
    const int acol = (tid & 3) << 2;

    const float* aptr0 = enc + (size_t)(m0 + arow) * CDn;
    const float* aptr1 = enc + (size_t)(m0 + arow + 64) * CDn;
    const float* bptr0 = cb + (size_t)(n0 + arow) * CDn;
    const float* bptr1 = cb + (size_t)(n0 + arow + 64) * CDn;

    float4 ra0, ra1, rb0, rb1;
    auto load_tile = [&](int kt) {
        const int k0 = kt * BK;
        ra0 = *reinterpret_cast<const float4*>(aptr0 + k0 + acol);
        ra1 = *reinterpret_cast<const float4*>(aptr1 + k0 + acol);
        rb0 = *reinterpret_cast<const float4*>(bptr0 + k0 + acol);
        rb1 = *reinterpret_cast<const float4*>(bptr1 + k0 + acol);
    };
    auto store_tile = [&](int b) {
        AS(b, acol + 0, arow) = ra0.x;
        AS(b, acol + 1, arow) = ra0.y;
        AS(b, acol + 2, arow) = ra0.z;
        AS(b, acol + 3, arow) = ra0.w;
        AS(b, acol + 0, arow + 64) = ra1.x;
        AS(b, acol + 1, arow + 64) = ra1.y;
        AS(b, acol + 2, arow + 64) = ra1.z;
        AS(b, acol + 3, arow + 64) = ra1.w;
        BS(b, acol + 0, arow) = rb0.x;
        BS(b, acol + 1, arow) = rb0.y;
        BS(b, acol + 2, arow) = rb0.z;
        BS(b, acol + 3, arow) = rb0.w;
        BS(b, acol + 0, arow + 64) = rb1.x;
        BS(b, acol + 1, arow + 64) = rb1.y;
        BS(b, acol + 2, arow + 64) = rb1.z;
        BS(b, acol + 3, arow + 64) = rb1.w;
    };

    float acc[8][8];
#pragma unroll
    for (int i = 0; i < 8; ++i)
#pragma unroll
        for (int j = 0; j < 8; ++j) acc[i][j] = 0.f;

    float e2acc = 0.f;                  // row `tid` sequential squared sum

    const int ntiles = CDn / BK;        // 16
    load_tile(0);
    store_tile(0);
    __syncthreads();
    int buf = 0;
    for (int kt = 0; kt < ntiles; ++kt) {
        const bool has_next = (kt + 1 < ntiles);
        if (has_next) load_tile(kt + 1);
#pragma unroll
        for (int k = 0; k < BK; ++k) {
            float a[8], bq[8];
            *reinterpret_cast<float4*>(&a[0])  = *reinterpret_cast<const float4*>(&AS(buf, k, ty * 4));
            *reinterpret_cast<float4*>(&a[4])  = *reinterpret_cast<const float4*>(&AS(buf, k, 64 + ty * 4));
            *reinterpret_cast<float4*>(&bq[0]) = *reinterpret_cast<const float4*>(&BS(buf, k, tx * 4));
            *reinterpret_cast<float4*>(&bq[4]) = *reinterpret_cast<const float4*>(&BS(buf, k, 64 + tx * 4));
#pragma unroll
            for (int i = 0; i < 8; ++i)
#pragma unroll
                for (int j = 0; j < 8; ++j)
                    acc[i][j] = fmaf(a[i], bq[j], acc[i][j]);
        }
        // fused ||enc||^2: ascending k within ascending kt (exact order)
        if (tid < BM) {
#pragma unroll
            for (int k = 0; k < BK; ++k) {
                const float v = AS(buf, k, tid);
                e2acc = __fadd_rn(e2acc, __fmul_rn(v, v));
            }
        }
        if (has_next) {
            store_tile(buf ^ 1);
            __syncthreads();
            buf ^= 1;
        }
    }

    if (tid < BM) e2s[tid] = e2acc;

    int rows[8];
#pragma unroll
    for (int i = 0; i < 4; ++i) { rows[i] = ty * 4 + i; rows[i + 4] = 64 + ty * 4 + i; }

    __syncthreads();                    // e2s ready; also fences SM reuse below

    float e2[8];
#pragma unroll
    for (int i = 0; i < 8; ++i) e2[i] = e2s[rows[i]];

    float bestv[8];
    int   besti[8];
#pragma unroll
    for (int i = 0; i < 8; ++i) { bestv[i] = FLT_MAX; besti[i] = 0; }

#pragma unroll
    for (int j = 0; j < 8; ++j) {
        const int c = n0 + ((j < 4) ? (tx * 4 + j) : (64 + tx * 4 + j - 4));
        const float cn = cbn[c];
#pragma unroll
        for (int i = 0; i < 8; ++i) {
            const float d = __fadd_rn(
                __fsub_rn(e2[i], __fmul_rn(2.0f, acc[i][j])), cn);
            if (d < bestv[i] || (d == bestv[i] && c < besti[i])) {
                bestv[i] = d; besti[i] = c;
            }
        }
    }

    // cross-thread reduction (16 tx-threads per token row) via SM pool
    float* redv = &SM[0];
    int*   redi = reinterpret_cast<int*>(&SM[2048]);
#pragma unroll
    for (int i = 0; i < 8; ++i) {
        redv[rows[i] * 16 + tx] = bestv[i];
        redi[rows[i] * 16 + tx] = besti[i];
    }
    __syncthreads();
    if (tid < BM) {
        float bv = redv[tid * 16];
        int   bi = redi[tid * 16];
#pragma unroll
        for (int t = 1; t < 16; ++t) {
            const float v = redv[tid * 16 + t];
            const int  ii = redi[tid * 16 + t];
            if (v < bv || (v == bv && ii < bi)) { bv = v; bi = ii; }
        }
        pbv[(size_t)chunk * MTOK + m0 + tid] = bv;
        pbi[(size_t)chunk * MTOK + m0 + tid] = bi;
    }
}

// ---------------------------------------------------------------------------
// final argmin over 8 chunk partials (exact lowest-index tie-break)
// ---------------------------------------------------------------------------
__global__ void __launch_bounds__(256)
argmin_reduce_kernel(const float* __restrict__ pbv,
                     const int*   __restrict__ pbi,
                     int* __restrict__ idxOut,
                     float* __restrict__ idxFloat)
{
    const int m = blockIdx.x * 256 + threadIdx.x;
    float bv = pbv[m];
    int   bi = pbi[m];
#pragma unroll
    for (int c = 1; c < 8; ++c) {
        const float v = pbv[(size_t)c * MTOK + m];
        const int  ii = pbi[(size_t)c * MTOK + m];
        if (v < bv || (v == bv && ii < bi)) { bv = v; bi = ii; }
    }
    idxOut[m] = bi;
    if (idxFloat) idxFloat[m] = (float)bi;
}

// ---------------------------------------------------------------------------
// host launcher
// ---------------------------------------------------------------------------
extern "C" void kernel_launch(void* const* d_in, const int* in_sizes, int n_in,
                              void* d_out, int out_size)
{
    const float* z   = (const float*)d_in[0];
    const float* ipw = (const float*)d_in[1];
    const float* ipb = (const float*)d_in[2];
    const float* inw = (const float*)d_in[3];
    const float* inb = (const float*)d_in[4];
    const float* cbk = (const float*)d_in[5];
    const float* oww = (const float*)d_in[6];
    const float* owb = (const float*)d_in[7];
    const float* opw = (const float*)d_in[8];
    const float* opb = (const float*)d_in[9];
    float* outF = (float*)d_out;

    float *gx, *gres, *genc, *gcbn, *gpbv;
    int *gidx, *gpbi;
    cudaGetSymbolAddress((void**)&gx,   g_x);
    cudaGetSymbolAddress((void**)&gres, g_res);
    cudaGetSymbolAddress((void**)&genc, g_enc);
    cudaGetSymbolAddress((void**)&gcbn, g_cbn);
    cudaGetSymbolAddress((void**)&gidx, g_idx);
    cudaGetSymbolAddress((void**)&gpbv, g_pbv);
    cudaGetSymbolAddress((void**)&gpbi, g_pbi);

    const dim3 blk(256);
    const long long OUT0 = (long long)8 * DOUT * TDIM;
    const bool writeIdx = (long long)out_size >= OUT0 + (long long)NQn * MTOK;

    // 0. all codebook norms (independent of pipeline) — one launch
    cbnorm_all_kernel<<<NQn * CSn / 32, blk>>>(cbk, gcbn);

    // 1. input projection: x (and residual copy)
    gemm_kernel<1, 0><<<dim3(RVQn / BN, MTOK / BM), blk>>>(
        z, nullptr, nullptr, ipw, ipb, gx, gres, DIN, RVQn);

    // 2. RVQ stages
    for (int q = 0; q < NQn; ++q) {
        const float* cbq = cbk + (size_t)q * CSn * CDn;
        gemm_kernel<0, 0><<<dim3(CDn / BN, MTOK / BM), blk>>>(
            gres, nullptr, nullptr,
            inw + (size_t)q * CDn * RVQn, inb + (size_t)q * CDn,
            genc, nullptr, RVQn, CDn);
        dist_partial_kernel<<<dim3(MTOK / BM, CSn / BN), blk>>>(
            genc, cbq, gcbn + (size_t)q * CSn, gpbv, gpbi);
        float* idxF = writeIdx ? (outF + OUT0 + (size_t)q * MTOK) : nullptr;
        argmin_reduce_kernel<<<MTOK / 256, blk>>>(gpbv, gpbi, gidx, idxF);
        gemm_kernel<2, 1><<<dim3(RVQn / BN, MTOK / BM), blk>>>(
            cbq, nullptr, gidx,
            oww + (size_t)q * RVQn * CDn, owb + (size_t)q * RVQn,
            gres, nullptr, CDn, RVQn);
    }

    // 3. output projection on emb = x - res, transposed store
    gemm_kernel<3, 2><<<dim3(DOUT / BN, MTOK / BM), blk>>>(
        gx, gres, nullptr, opw, opb, outF, nullptr, RVQn, DOUT);
}

// round 10
// speedup vs baseline: 1.5948x; 1.2268x over previous
#include <cuda_runtime.h>
#include <cfloat>

// ---------------------------------------------------------------------------
// ResidualVQ on GB300 — round 5: exact-fp32 pipeline.
//   * NEW: out-projection factored through the codebook:
//       Wc[q][k][d] = sum_c cb[q][k][c] * out_w[q][d][c]   (one batched GEMM)
//     and the per-stage residual update becomes a bit-identical row gather:
//       res[m][:] -= Wc[q][idx[m]][:] + out_b[q]
//   * argmin-reduce fused into the gather kernel (one warp/token)
//   * dist split over 8 code chunks, fused ||enc||^2, double-buffered GEMMs
// All argmin-critical numerics unchanged: ascending-k single-acc fma chains,
// sequential scalar row norms, d = fadd(fsub(enc2, fmul(2,dot)), cbn).
// ---------------------------------------------------------------------------

#define BM 128
#define BN 128
#define BK 16

#define MTOK 16384
#define TDIM 2048
#define DIN  768
#define RVQn 512
#define NQn  8
#define CSn  1024
#define CDn  256
#define DOUT 768

// scratch (device globals; no allocation allowed)
__device__ float g_x   [MTOK * RVQn];
__device__ float g_res [MTOK * RVQn];
__device__ float g_enc [MTOK * CDn];
__device__ float g_cbn [NQn * CSn];          // all-stage codebook norms
__device__ float g_wc  [NQn * CSn * RVQn];   // precomputed out_w @ cb^T, k-major
__device__ float g_pbv [8 * MTOK];           // per-chunk partial best value
__device__ int   g_pbi [8 * MTOK];           // per-chunk partial best index

// shared-memory pool indexing
#define AS(b,k,m) SM[(b)*(BK*BM) + (k)*BM + (m)]
#define BS(b,k,n) SM[2*(BK*BM) + (b)*(BK*BN) + (k)*BN + (n)]

// ---------------------------------------------------------------------------
// Unified SGEMM: C[m,n] = sum_k A[m,k] * B[n,k]   (B always (N x K) row-major)
// AMODE: 0 = A row-major; 1 = A is z (B,DIN,T) transposed view;
//        3 = A - A2 row-major.
// EPI:   0 = C = acc + bias (+ optional dup store C2)
//        2 = transposed store into (B, DOUT, T) with bias
//        3 = raw store C = acc (no bias) — used for the Wc precompute
// Batched over blockIdx.z with strides qsA/qsB/qsC (pass 0 when unbatched).
// ---------------------------------------------------------------------------
template<int AMODE, int EPI>
__global__ void __launch_bounds__(256, 2)
gemm_kernel(const float* __restrict__ A,
            const float* __restrict__ A2,
            const float* __restrict__ B,
            const float* __restrict__ bias,
            float* __restrict__ C,
            float* __restrict__ C2,
            int K, int N,
            size_t qsA, size_t qsB, size_t qsC)
{
    __shared__ float SM[2*BK*BM + 2*BK*BN];   // 32 KB

    const int q = blockIdx.z;
    A += (size_t)q * qsA;
    B += (size_t)q * qsB;
    C += (size_t)q * qsC;

    const int tid = threadIdx.x;
    const int m0  = blockIdx.y * BM;
    const int n0  = blockIdx.x * BN;

    const int tx = tid & 15;
    const int ty = tid >> 4;

    const int arow = tid >> 2;          // 0..63
    const int acol = (tid & 3) << 2;    // 0,4,8,12

    const float* aptr0 = nullptr;
    const float* aptr1 = nullptr;
    if constexpr (AMODE == 0 || AMODE == 3) {
        aptr0 = A + (size_t)(m0 + arow) * K;
        aptr1 = A + (size_t)(m0 + arow + 64) * K;
    }
    const float* zb = nullptr;
    int t0z = 0, zk = 0, zm = 0;
    if constexpr (AMODE == 1) {
        const int b = m0 >> 11;
        t0z = m0 & (TDIM - 1);
        zb  = A + (size_t)b * DIN * TDIM;
        zk  = tid >> 5;
        zm  = (tid & 31) << 2;
    }
    const float* bptr0 = B + (size_t)(n0 + arow) * K;
    const float* bptr1 = B + (size_t)(n0 + arow + 64) * K;

    float4 ra0, ra1, rb0, rb1;

    auto load_tile = [&](int kt) {
        const int k0 = kt * BK;
        if constexpr (AMODE == 1) {
            ra0 = *reinterpret_cast<const float4*>(zb + (size_t)(k0 + zk)     * TDIM + t0z + zm);
            ra1 = *reinterpret_cast<const float4*>(zb + (size_t)(k0 + zk + 8) * TDIM + t0z + zm);
        } else {
            ra0 = *reinterpret_cast<const float4*>(aptr0 + k0 + acol);
            ra1 = *reinterpret_cast<const float4*>(aptr1 + k0 + acol);
            if constexpr (AMODE == 3) {
                float4 r0 = *reinterpret_cast<const float4*>(A2 + (size_t)(m0 + arow)      * K + k0 + acol);
                float4 r1 = *reinterpret_cast<const float4*>(A2 + (size_t)(m0 + arow + 64) * K + k0 + acol);
                ra0.x = __fsub_rn(ra0.x, r0.x); ra0.y = __fsub_rn(ra0.y, r0.y);
                ra0.z = __fsub_rn(ra0.z, r0.z); ra0.w = __fsub_rn(ra0.w, r0.w);
                ra1.x = __fsub_rn(ra1.x, r1.x); ra1.y = __fsub_rn(ra1.y, r1.y);
                ra1.z = __fsub_rn(ra1.z, r1.z); ra1.w = __fsub_rn(ra1.w, r1.w);
            }
        }
        rb0 = *reinterpret_cast<const float4*>(bptr0 + k0 + acol);
        rb1 = *reinterpret_cast<const float4*>(bptr1 + k0 + acol);
    };

    auto store_tile = [&](int b) {
        if constexpr (AMODE == 1) {
            *reinterpret_cast<float4*>(&AS(b, zk,     zm)) = ra0;
            *reinterpret_cast<float4*>(&AS(b, zk + 8, zm)) = ra1;
        } else {
            AS(b, acol + 0, arow) = ra0.x;
            AS(b, acol + 1, arow) = ra0.y;
            AS(b, acol + 2, arow) = ra0.z;
            AS(b, acol + 3, arow) = ra0.w;
            AS(b, acol + 0, arow + 64) = ra1.x;
            AS(b, acol + 1, arow + 64) = ra1.y;
            AS(b, acol + 2, arow + 64) = ra1.z;
            AS(b, acol + 3, arow + 64) = ra1.w;
        }
        BS(b, acol + 0, arow) = rb0.x;
        BS(b, acol + 1, arow) = rb0.y;
        BS(b, acol + 2, arow) = rb0.z;
        BS(b, acol + 3, arow) = rb0.w;
        BS(b, acol + 0, arow + 64) = rb1.x;
        BS(b, acol + 1, arow + 64) = rb1.y;
        BS(b, acol + 2, arow + 64) = rb1.z;
        BS(b, acol + 3, arow + 64) = rb1.w;
    };

    float acc[8][8];
#pragma unroll
    for (int i = 0; i < 8; ++i)
#pragma unroll
        for (int j = 0; j < 8; ++j) acc[i][j] = 0.f;

    auto compute = [&](int b) {
#pragma unroll
        for (int k = 0; k < BK; ++k) {
            float a[8], bq[8];
            *reinterpret_cast<float4*>(&a[0])  = *reinterpret_cast<const float4*>(&AS(b, k, ty * 4));
            *reinterpret_cast<float4*>(&a[4])  = *reinterpret_cast<const float4*>(&AS(b, k, 64 + ty * 4));
            *reinterpret_cast<float4*>(&bq[0]) = *reinterpret_cast<const float4*>(&BS(b, k, tx * 4));
            *reinterpret_cast<float4*>(&bq[4]) = *reinterpret_cast<const float4*>(&BS(b, k, 64 + tx * 4));
#pragma unroll
            for (int i = 0; i < 8; ++i)
#pragma unroll
                for (int j = 0; j < 8; ++j)
                    acc[i][j] = fmaf(a[i], bq[j], acc[i][j]);
        }
    };

    const int ntiles = K / BK;
    load_tile(0);
    store_tile(0);
    __syncthreads();
    int buf = 0;
    for (int kt = 0; kt < ntiles; ++kt) {
        const bool has_next = (kt + 1 < ntiles);
        if (has_next) load_tile(kt + 1);
        compute(buf);
        if (has_next) {
            store_tile(buf ^ 1);
            __syncthreads();
            buf ^= 1;
        }
    }

    int rows[8];
#pragma unroll
    for (int i = 0; i < 4; ++i) { rows[i] = ty * 4 + i; rows[i + 4] = 64 + ty * 4 + i; }

    if constexpr (EPI == 0 || EPI == 3) {
#pragma unroll
        for (int i = 0; i < 8; ++i) {
            const size_t r = (size_t)(m0 + rows[i]);
#pragma unroll
            for (int g = 0; g < 2; ++g) {
                const int c = n0 + (g ? 64 : 0) + tx * 4;
                float4 v;
                if constexpr (EPI == 0) {
                    const float4 bv = *reinterpret_cast<const float4*>(bias + c);
                    v.x = __fadd_rn(acc[i][g * 4 + 0], bv.x);
                    v.y = __fadd_rn(acc[i][g * 4 + 1], bv.y);
                    v.z = __fadd_rn(acc[i][g * 4 + 2], bv.z);
                    v.w = __fadd_rn(acc[i][g * 4 + 3], bv.w);
                } else {
                    v.x = acc[i][g * 4 + 0];
                    v.y = acc[i][g * 4 + 1];
                    v.z = acc[i][g * 4 + 2];
                    v.w = acc[i][g * 4 + 3];
                }
                *reinterpret_cast<float4*>(C + r * N + c) = v;
                if (EPI == 0 && C2) *reinterpret_cast<float4*>(C2 + r * N + c) = v;
            }
        }
    }

    if constexpr (EPI == 2) {
        float* Cs = &SM[0];                      // [32][BM+4]
        const int b   = m0 >> 11;
        const int t0e = m0 & (TDIM - 1);
        __syncthreads();
#pragma unroll
        for (int s = 0; s < 4; ++s) {
            const int g = s >> 1;
            if ((tx >> 3) == (s & 1)) {
                const int cl = tx * 4 - 32 * (s & 1);
#pragma unroll
                for (int i = 0; i < 8; ++i)
#pragma unroll
                    for (int jj = 0; jj < 4; ++jj)
                        Cs[(cl + jj) * (BM + 4) + rows[i]] = acc[i][g * 4 + jj];
            }
            __syncthreads();
            for (int w = tid; w < 32 * BM; w += 256) {
                const int nl = w >> 7;
                const int tl = w & 127;
                const int n  = n0 + s * 32 + nl;
                C[((size_t)b * DOUT + n) * TDIM + t0e + tl] =
                    __fadd_rn(Cs[nl * (BM + 4) + tl], bias[n]);
            }
            __syncthreads();
        }
    }
}

// ---------------------------------------------------------------------------
// All codebook row norms in one launch (32 rows/block, sequential-ascending
// scalar mul+add per row — exact reference rounding).
// ---------------------------------------------------------------------------
__global__ void __launch_bounds__(256)
cbnorm_all_kernel(const float* __restrict__ CB, float* __restrict__ out)
{
    __shared__ float s[32][CDn + 1];
    const int tid = threadIdx.x;
    const int r0  = blockIdx.x * 32;
    for (int i = tid; i < 32 * CDn; i += 256) {
        const int t = i >> 8;
        const int c = i & (CDn - 1);
        s[t][c] = CB[(size_t)(r0 + t) * CDn + c];
    }
    __syncthreads();
    if (tid < 32) {
        float acc = 0.f;
#pragma unroll 8
        for (int c = 0; c < CDn; ++c) {
            const float v = s[tid][c];
            acc = __fadd_rn(acc, __fmul_rn(v, v));
        }
        out[r0 + tid] = acc;
    }
}

// ---------------------------------------------------------------------------
// dist partial with fused ||enc||^2 (sequential-ascending order preserved).
//   d = fadd( fsub( enc2, fmul(2, dot) ), cbn )
// ---------------------------------------------------------------------------
__global__ void __launch_bounds__(256, 2)
dist_partial_kernel(const float* __restrict__ enc,
                    const float* __restrict__ cb,
                    const float* __restrict__ cbn,
                    float* __restrict__ pbv,
                    int*   __restrict__ pbi)
{
    __shared__ float SM[2*BK*BM + 2*BK*BN];
    __shared__ float e2s[BM];

    const int tid   = threadIdx.x;
    const int m0    = blockIdx.x * BM;
    const int chunk = blockIdx.y;
    const int n0    = chunk * BN;

    const int tx = tid & 15;
    const int ty = tid >> 4;
    const int arow = tid >> 2;
    const int acol = (tid & 3) << 2;

    const float* aptr0 = enc + (size_t)(m0 + arow) * CDn;
    const float* aptr1 = enc + (size_t)(m0 + arow + 64) * CDn;
    const float* bptr0 = cb + (size_t)(n0 + arow) * CDn;
    const float* bptr1 = cb + (size_t)(n0 + arow + 64) * CDn;

    float4 ra0, ra1, rb0, rb1;
    auto load_tile = [&](int kt) {
        const int k0 = kt * BK;
        ra0 = *reinterpret_cast<const float4*>(aptr0 + k0 + acol);
        ra1 = *reinterpret_cast<const float4*>(aptr1 + k0 + acol);
        rb0 = *reinterpret_cast<const float4*>(bptr0 + k0 + acol);
        rb1 = *reinterpret_cast<const float4*>(bptr1 + k0 + acol);
    };
    auto store_tile = [&](int b) {
        AS(b, acol + 0, arow) = ra0.x;
        AS(b, acol + 1, arow) = ra0.y;
        AS(b, acol + 2, arow) = ra0.z;
        AS(b, acol + 3, arow) = ra0.w;
        AS(b, acol + 0, arow + 64) = ra1.x;
        AS(b, acol + 1, arow + 64) = ra1.y;
        AS(b, acol + 2, arow + 64) = ra1.z;
        AS(b, acol + 3, arow + 64) = ra1.w;
        BS(b, acol + 0, arow) = rb0.x;
        BS(b, acol + 1, arow) = rb0.y;
        BS(b, acol + 2, arow) = rb0.z;
        BS(b, acol + 3, arow) = rb0.w;
        BS(b, acol + 0, arow + 64) = rb1.x;
        BS(b, acol + 1, arow + 64) = rb1.y;
        BS(b, acol + 2, arow + 64) = rb1.z;
        BS(b, acol + 3, arow + 64) = rb1.w;
    };

    float acc[8][8];
#pragma unroll
    for (int i = 0; i < 8; ++i)
#pragma unroll
        for (int j = 0; j < 8; ++j) acc[i][j] = 0.f;

    float e2acc = 0.f;

    const int ntiles = CDn / BK;        // 16
    load_tile(0);
    store_tile(0);
    __syncthreads();
    int buf = 0;
    for (int kt = 0; kt < ntiles; ++kt) {
        const bool has_next = (kt + 1 < ntiles);
        if (has_next) load_tile(kt + 1);
#pragma unroll
        for (int k = 0; k < BK; ++k) {
            float a[8], bq[8];
            *reinterpret_cast<float4*>(&a[0])  = *reinterpret_cast<const float4*>(&AS(buf, k, ty * 4));
            *reinterpret_cast<float4*>(&a[4])  = *reinterpret_cast<const float4*>(&AS(buf, k, 64 + ty * 4));
            *reinterpret_cast<float4*>(&bq[0]) = *reinterpret_cast<const float4*>(&BS(buf, k, tx * 4));
            *reinterpret_cast<float4*>(&bq[4]) = *reinterpret_cast<const float4*>(&BS(buf, k, 64 + tx * 4));
#pragma unroll
            for (int i = 0; i < 8; ++i)
#pragma unroll
                for (int j = 0; j < 8; ++j)
                    acc[i][j] = fmaf(a[i], bq[j], acc[i][j]);
        }
        if (tid < BM) {
#pragma unroll
            for (int k = 0; k < BK; ++k) {
                const float v = AS(buf, k, tid);
                e2acc = __fadd_rn(e2acc, __fmul_rn(v, v));
            }
        }
        if (has_next) {
            store_tile(buf ^ 1);
            __syncthreads();
            buf ^= 1;
        }
    }

    if (tid < BM) e2s[tid] = e2acc;

    int rows[8];
#pragma unroll
    for (int i = 0; i < 4; ++i) { rows[i] = ty * 4 + i; rows[i + 4] = 64 + ty * 4 + i; }

    __syncthreads();

    float e2[8];
#pragma unroll
    for (int i = 0; i < 8; ++i) e2[i] = e2s[rows[i]];

    float bestv[8];
    int   besti[8];
#pragma unroll
    for (int i = 0; i < 8; ++i) { bestv[i] = FLT_MAX; besti[i] = 0; }

#pragma unroll
    for (int j = 0; j < 8; ++j) {
        const int c = n0 + ((j < 4) ? (tx * 4 + j) : (64 + tx * 4 + j - 4));
        const float cn = cbn[c];
#pragma unroll
        for (int i = 0; i < 8; ++i) {
            const float d = __fadd_rn(
                __fsub_rn(e2[i], __fmul_rn(2.0f, acc[i][j])), cn);
            if (d < bestv[i] || (d == bestv[i] && c < besti[i])) {
                bestv[i] = d; besti[i] = c;
            }
        }
    }

    float* redv = &SM[0];
    int*   redi = reinterpret_cast<int*>(&SM[2048]);
#pragma unroll
    for (int i = 0; i < 8; ++i) {
        redv[rows[i] * 16 + tx] = bestv[i];
        redi[rows[i] * 16 + tx] = besti[i];
    }
    __syncthreads();
    if (tid < BM) {
        float bv = redv[tid * 16];
        int   bi = redi[tid * 16];
#pragma unroll
        for (int t = 1; t < 16; ++t) {
            const float v = redv[tid * 16 + t];
            const int  ii = redi[tid * 16 + t];
            if (v < bv || (v == bv && ii < bi)) { bv = v; bi = ii; }
        }
        pbv[(size_t)chunk * MTOK + m0 + tid] = bv;
        pbi[(size_t)chunk * MTOK + m0 + tid] = bi;
    }
}

// ---------------------------------------------------------------------------
// fused argmin-reduce + residual gather update. One warp per token:
//   lane 0 reduces the 8 chunk partials (exact lowest-index tie-break),
//   broadcasts idx, then the warp does res[m][:] -= Wc[idx][:] + out_b.
// Rounding sequence identical to the former GEMM epilogue:
//   v = fadd(wc, bias); res = fsub(res, v).
// ---------------------------------------------------------------------------
__global__ void __launch_bounds__(256)
gather_update_kernel(const float* __restrict__ pbv,
                     const int*   __restrict__ pbi,
                     const float* __restrict__ wc,    // [CSn][RVQn] for stage q
                     const float* __restrict__ ob,    // out_b[q], RVQn
                     float* __restrict__ res,
                     float* __restrict__ idxFloat)
{
    const int warp = (blockIdx.x * blockDim.x + threadIdx.x) >> 5;
    const int lane = threadIdx.x & 31;
    const int m = warp;
    if (m >= MTOK) return;

    int bi = 0;
    if (lane == 0) {
        float bv = pbv[m];
        bi = pbi[m];
#pragma unroll
        for (int c = 1; c < 8; ++c) {
            const float v = pbv[(size_t)c * MTOK + m];
            const int  ii = pbi[(size_t)c * MTOK + m];
            if (v < bv || (v == bv && ii < bi)) { bv = v; bi = ii; }
        }
        if (idxFloat) idxFloat[m] = (float)bi;
    }
    bi = __shfl_sync(0xffffffffu, bi, 0);

    const float4* wrow = reinterpret_cast<const float4*>(wc + (size_t)bi * RVQn);
    const float4* brow = reinterpret_cast<const float4*>(ob);
    float4*       rrow = reinterpret_cast<float4*>(res + (size_t)m * RVQn);
#pragma unroll
    for (int i = lane; i < RVQn / 4; i += 32) {
        const float4 w = wrow[i];
        const float4 b = brow[i];
        float4 r = rrow[i];
        r.x = __fsub_rn(r.x, __fadd_rn(w.x, b.x));
        r.y = __fsub_rn(r.y, __fadd_rn(w.y, b.y));
        r.z = __fsub_rn(r.z, __fadd_rn(w.z, b.z));
        r.w = __fsub_rn(r.w, __fadd_rn(w.w, b.w));
        rrow[i] = r;
    }
}

// ---------------------------------------------------------------------------
// host launcher
// ---------------------------------------------------------------------------
extern "C" void kernel_launch(void* const* d_in, const int* in_sizes, int n_in,
                              void* d_out, int out_size)
{
    const float* z   = (const float*)d_in[0];
    const float* ipw = (const float*)d_in[1];
    const float* ipb = (const float*)d_in[2];
    const float* inw = (const float*)d_in[3];
    const float* inb = (const float*)d_in[4];
    const float* cbk = (const float*)d_in[5];
    const float* oww = (const float*)d_in[6];
    const float* owb = (const float*)d_in[7];
    const float* opw = (const float*)d_in[8];
    const float* opb = (const float*)d_in[9];
    float* outF = (float*)d_out;

    float *gx, *gres, *genc, *gcbn, *gwc, *gpbv;
    int *gpbi;
    cudaGetSymbolAddress((void**)&gx,   g_x);
    cudaGetSymbolAddress((void**)&gres, g_res);
    cudaGetSymbolAddress((void**)&genc, g_enc);
    cudaGetSymbolAddress((void**)&gcbn, g_cbn);
    cudaGetSymbolAddress((void**)&gwc,  g_wc);
    cudaGetSymbolAddress((void**)&gpbv, g_pbv);
    cudaGetSymbolAddress((void**)&gpbi, g_pbi);

    const dim3 blk(256);
    const long long OUT0 = (long long)8 * DOUT * TDIM;
    const bool writeIdx = (long long)out_size >= OUT0 + (long long)NQn * MTOK;

    // 0a. all codebook norms — one launch
    cbnorm_all_kernel<<<NQn * CSn / 32, blk>>>(cbk, gcbn);

    // 0b. Wc[q][k][d] = sum_c cb[q][k][c] * out_w[q][d][c]  — one batched GEMM
    //     M = CSn (codes), N = RVQn, K = CDn. Bit-identical ascending-c fma.
    gemm_kernel<0, 3><<<dim3(RVQn / BN, CSn / BM, NQn), blk>>>(
        cbk, nullptr, oww, nullptr, gwc, nullptr, CDn, RVQn,
        (size_t)CSn * CDn, (size_t)RVQn * CDn, (size_t)CSn * RVQn);

    // 1. input projection: x (and residual copy)
    gemm_kernel<1, 0><<<dim3(RVQn / BN, MTOK / BM), blk>>>(
        z, nullptr, ipw, ipb, gx, gres, DIN, RVQn, 0, 0, 0);

    // 2. RVQ stages
    for (int q = 0; q < NQn; ++q) {
        const float* cbq = cbk + (size_t)q * CSn * CDn;
        gemm_kernel<0, 0><<<dim3(CDn / BN, MTOK / BM), blk>>>(
            gres, nullptr,
            inw + (size_t)q * CDn * RVQn, inb + (size_t)q * CDn,
            genc, nullptr, RVQn, CDn, 0, 0, 0);
        dist_partial_kernel<<<dim3(MTOK / BM, CSn / BN), blk>>>(
            genc, cbq, gcbn + (size_t)q * CSn, gpbv, gpbi);
        float* idxF = writeIdx ? (outF + OUT0 + (size_t)q * MTOK) : nullptr;
        gather_update_kernel<<<(MTOK * 32) / 256, blk>>>(
            gpbv, gpbi, gwc + (size_t)q * CSn * RVQn, owb + (size_t)q * RVQn,
            gres, idxF);
    }

    // 3. output projection on emb = x - res, transposed store
    gemm_kernel<3, 2><<<dim3(DOUT / BN, MTOK / BM), blk>>>(
        gx, gres, opw, opb, outF, nullptr, RVQn, DOUT, 0, 0, 0);
}